// round 9
// baseline (speedup 1.0000x reference)
#include <cuda_runtime.h>
#include <cstdint>
#include <math_constants.h>

#define T_DIM 64
#define B_DIM 32
#define S_DIM 128
#define E_DIM 512
#define Q_DIM 512
#define H_DIM 256

#define GEMM_BK   32
#define GEMM_PAD  36   // floats per smem row (32 data + 4 pad): conflict-free frags

// Scratch (device globals — no allocation allowed)
__device__ float g_src_proj[B_DIM * H_DIM * S_DIM];   // [b][h][s]
__device__ float g_q_proj[T_DIM * B_DIM * H_DIM];     // [t][b][h]

__device__ __forceinline__ float ex2f_(float x) {
    float y; asm("ex2.approx.f32 %0, %1;" : "=f"(y) : "f"(x)); return y;
}
__device__ __forceinline__ float tanhf_(float x) {
    float y; asm("tanh.approx.f32 %0, %1;" : "=f"(y) : "f"(x)); return y;
}
__device__ __forceinline__ void mma_tf32(float c[4], const unsigned a[4], const unsigned b[2]) {
    asm volatile(
        "mma.sync.aligned.m16n8k8.row.col.f32.tf32.tf32.f32 "
        "{%0,%1,%2,%3}, {%4,%5,%6,%7}, {%8,%9}, {%0,%1,%2,%3};"
        : "+f"(c[0]), "+f"(c[1]), "+f"(c[2]), "+f"(c[3])
        : "r"(a[0]), "r"(a[1]), "r"(a[2]), "r"(a[3]), "r"(b[0]), "r"(b[1]));
}
__device__ __forceinline__ void cp_async16(uint32_t saddr, const void* gptr) {
    asm volatile("cp.async.cg.shared.global [%0], [%1], 16;" :: "r"(saddr), "l"(gptr));
}

// ---------------------------------------------------------------------------
// Tensor-core projection GEMM — TF32, cp.async double-buffered (unchanged).
// ---------------------------------------------------------------------------
__global__ __launch_bounds__(512) void proj_gemm(
    const float* __restrict__ src, const float* __restrict__ Wsrc, const float* __restrict__ bsrc,
    const float* __restrict__ qv,  const float* __restrict__ Wq,   const float* __restrict__ bq)
{
    extern __shared__ float sm[];
    float* As = sm;                        // [2][128][GEMM_PAD]
    float* Bs = sm + 2 * 128 * GEMM_PAD;   // [2][64][GEMM_PAD]

    const int bx = blockIdx.x;      // 0..47
    const int n0 = blockIdx.y * 64; // h tile base

    const bool is_src = (bx < 32);
    const float* __restrict__ A    = is_src ? (src + (size_t)bx * 128 * E_DIM)
                                            : (qv  + (size_t)(bx - 32) * 128 * Q_DIM);
    const float* __restrict__ W    = is_src ? Wsrc : Wq;
    const float* __restrict__ bias = is_src ? bsrc : bq;

    const int tid  = threadIdx.x;
    const int warp = tid >> 5;
    const int lane = tid & 31;
    const int wm   = (warp & 3) * 32;
    const int wn   = (warp >> 2) * 16;
    const int frow = lane >> 2;
    const int fcol = lane & 3;

    const uint32_t As_base = (uint32_t)__cvta_generic_to_shared(As);
    const uint32_t Bs_base = (uint32_t)__cvta_generic_to_shared(Bs);

    float acc[2][2][4];
#pragma unroll
    for (int i = 0; i < 2; i++)
#pragma unroll
        for (int j = 0; j < 2; j++)
#pragma unroll
            for (int r = 0; r < 4; r++) acc[i][j][r] = 0.f;

    auto load_chunk = [&](int kc, int buf) {
        const int kt = kc * GEMM_BK;
        const uint32_t abuf = As_base + (uint32_t)buf * 128 * GEMM_PAD * 4;
        const uint32_t bbuf = Bs_base + (uint32_t)buf * 64 * GEMM_PAD * 4;
#pragma unroll
        for (int j = 0; j < 2; j++) {
            const int v = tid + j * 512;
            const int r = v >> 3;
            const int c = (v & 7) * 4;
            cp_async16(abuf + (uint32_t)(r * GEMM_PAD + c) * 4,
                       &A[(size_t)r * 512 + kt + c]);
        }
        {
            const int r = tid >> 3;
            const int c = (tid & 7) * 4;
            cp_async16(bbuf + (uint32_t)(r * GEMM_PAD + c) * 4,
                       &W[(size_t)(n0 + r) * 512 + kt + c]);
        }
        asm volatile("cp.async.commit_group;");
    };

    load_chunk(0, 0);

    for (int kc = 0; kc < 16; kc++) {
        if (kc + 1 < 16) {
            load_chunk(kc + 1, (kc + 1) & 1);
            asm volatile("cp.async.wait_group 1;");
        } else {
            asm volatile("cp.async.wait_group 0;");
        }
        __syncthreads();

        const int buf = kc & 1;
        const float* Ab = As + buf * 128 * GEMM_PAD;
        const float* Bb = Bs + buf * 64 * GEMM_PAD;

#pragma unroll
        for (int ks = 0; ks < 4; ks++) {
            const int k0 = ks * 8;
            unsigned ah[2][4];
#pragma unroll
            for (int mf = 0; mf < 2; mf++) {
                const int m = wm + mf * 16;
                ah[mf][0] = __float_as_uint(Ab[(m + frow    ) * GEMM_PAD + k0 + fcol    ]);
                ah[mf][1] = __float_as_uint(Ab[(m + frow + 8) * GEMM_PAD + k0 + fcol    ]);
                ah[mf][2] = __float_as_uint(Ab[(m + frow    ) * GEMM_PAD + k0 + fcol + 4]);
                ah[mf][3] = __float_as_uint(Ab[(m + frow + 8) * GEMM_PAD + k0 + fcol + 4]);
            }
            unsigned bh[2][2];
#pragma unroll
            for (int nf = 0; nf < 2; nf++) {
                const int n = wn + nf * 8;
                bh[nf][0] = __float_as_uint(Bb[(n + frow) * GEMM_PAD + k0 + fcol    ]);
                bh[nf][1] = __float_as_uint(Bb[(n + frow) * GEMM_PAD + k0 + fcol + 4]);
            }
#pragma unroll
            for (int mf = 0; mf < 2; mf++)
#pragma unroll
                for (int nf = 0; nf < 2; nf++)
                    mma_tf32(acc[mf][nf], ah[mf], bh[nf]);
        }
        __syncthreads();
    }

    const int crow = lane >> 2;
    const int ccol = (lane & 3) * 2;

    if (is_src) {
        const int b = bx;
        float* dst = g_src_proj + (size_t)b * H_DIM * S_DIM;
#pragma unroll
        for (int mf = 0; mf < 2; mf++)
#pragma unroll
            for (int nf = 0; nf < 2; nf++) {
                const int s0  = wm + mf * 16 + crow;
                const int h0g = n0 + wn + nf * 8 + ccol;
                dst[(h0g    ) * S_DIM + s0    ] = acc[mf][nf][0] + bias[h0g    ];
                dst[(h0g + 1) * S_DIM + s0    ] = acc[mf][nf][1] + bias[h0g + 1];
                dst[(h0g    ) * S_DIM + s0 + 8] = acc[mf][nf][2] + bias[h0g    ];
                dst[(h0g + 1) * S_DIM + s0 + 8] = acc[mf][nf][3] + bias[h0g + 1];
            }
    } else {
        const int m0 = (bx - 32) * 128;
#pragma unroll
        for (int mf = 0; mf < 2; mf++)
#pragma unroll
            for (int nf = 0; nf < 2; nf++) {
                const int m   = m0 + wm + mf * 16 + crow;
                const int h0g = n0 + wn + nf * 8 + ccol;
                g_q_proj[(size_t)m * H_DIM + h0g    ]       = acc[mf][nf][0] + bias[h0g    ];
                g_q_proj[(size_t)m * H_DIM + h0g + 1]       = acc[mf][nf][1] + bias[h0g + 1];
                g_q_proj[(size_t)(m + 8) * H_DIM + h0g    ] = acc[mf][nf][2] + bias[h0g    ];
                g_q_proj[(size_t)(m + 8) * H_DIM + h0g + 1] = acc[mf][nf][3] + bias[h0g + 1];
            }
    }
}

// ---------------------------------------------------------------------------
// Fused kernel (TT=4, 512 CTAs — proven structure), MIXED-PIPE tanh:
//   tt 0,1: MUFU.TANH  (16 cyc MUFU each, hypothesis)
//   tt 2,3: tanh = 1 - 2/(1+ex2(2x*log2e)): ex2 (8 cyc MUFU) + bit-magic rcp
//           refined by 2 Newton iterations on the FMA pipe (err ~1e-5).
// qs rows 2,3 are pre-scaled by 2*log2(e) at fill time.
// part[tt][hg][s]: for tt 0,1 stores sum(w*tanh); for tt 2,3 stores
// (sum_w_quarter - 2*sum(w*r)) so summing the 4 hg parts gives the logit core.
// ---------------------------------------------------------------------------
__global__ __launch_bounds__(512) void fused_attn(
    const float* __restrict__ w2, const float* __restrict__ b2p,
    const int* __restrict__ mask, float* __restrict__ out)
{
    const int b   = blockIdx.y;
    const int tg  = blockIdx.x;
    const int tid = threadIdx.x;
    const int s   = tid & 127;
    const int hg  = tid >> 7;

    __shared__ float qs[4][H_DIM];
    __shared__ float w2s[H_DIM];
    __shared__ float part[4][4][S_DIM];
    __shared__ float redm[4][4];
    __shared__ float reds[4][4];

    const float LOG2E     = 1.442695040888963407f;
    const float TWO_LOG2E = 2.885390081777926815f;

    for (int idx = tid; idx < 4 * H_DIM; idx += 512) {
        const int tt = idx >> 8;
        const int h  = idx & (H_DIM - 1);
        const int t  = tg * 4 + tt;
        const float q = g_q_proj[((size_t)t * B_DIM + b) * H_DIM + h];
        qs[tt][h] = (tt >= 2) ? q * TWO_LOG2E : q;   // pre-scale Newton rows
    }
    if (tid < H_DIM) w2s[tid] = w2[tid];
    __syncthreads();

    const float* __restrict__ srcb = g_src_proj + (size_t)b * H_DIM * S_DIM + s;
    const int h0 = hg * 64;

    float a0 = 0.f, a1 = 0.f, a2 = 0.f, a3 = 0.f, wsum = 0.f;
#pragma unroll 4
    for (int i = 0; i < 64; i++) {
        const int h = h0 + i;
        const float sv = srcb[h * S_DIM];
        const float w  = w2s[h];
        wsum += w;
        // --- TANH path (tt 0,1) ---
        a0 = fmaf(w, tanhf_(sv + qs[0][h]), a0);
        a1 = fmaf(w, tanhf_(sv + qs[1][h]), a1);
        // --- ex2 + Newton-rcp path (tt 2,3): r = 1/(1+e^{2x}) ---
        {
            const float y = fmaf(sv, TWO_LOG2E, qs[2][h]);
            const float d = ex2f_(y) + 1.f;
            float r = __uint_as_float(0x7EF311C3u - __float_as_uint(d));
            r = r * fmaf(-d, r, 2.f);
            r = r * fmaf(-d, r, 2.f);
            a2 = fmaf(w, r, a2);
        }
        {
            const float y = fmaf(sv, TWO_LOG2E, qs[3][h]);
            const float d = ex2f_(y) + 1.f;
            float r = __uint_as_float(0x7EF311C3u - __float_as_uint(d));
            r = r * fmaf(-d, r, 2.f);
            r = r * fmaf(-d, r, 2.f);
            a3 = fmaf(w, r, a3);
        }
    }
    part[0][hg][s] = a0;
    part[1][hg][s] = a1;
    part[2][hg][s] = fmaf(-2.f, a2, wsum);   // sum w*tanh over quarter
    part[3][hg][s] = fmaf(-2.f, a3, wsum);
    __syncthreads();

    float logit = ((part[hg][0][s] + part[hg][1][s]) +
                   (part[hg][2][s] + part[hg][3][s])) + b2p[0];
    if (mask[b * S_DIM + s] != 0)
        logit = __int_as_float(0xff800000);

    const int lane = tid & 31;
    const int gw   = (tid >> 5) & 3;

    float m = logit;
#pragma unroll
    for (int off = 16; off >= 1; off >>= 1)
        m = fmaxf(m, __shfl_xor_sync(0xffffffffu, m, off));
    if (lane == 0) redm[hg][gw] = m;
    __syncthreads();

    const float bm = fmaxf(fmaxf(redm[hg][0], redm[hg][1]),
                           fmaxf(redm[hg][2], redm[hg][3]));
    const float e = ex2f_((logit - bm) * LOG2E);
    float sum = e;
#pragma unroll
    for (int off = 16; off >= 1; off >>= 1)
        sum += __shfl_xor_sync(0xffffffffu, sum, off);
    if (lane == 0) reds[hg][gw] = sum;
    __syncthreads();

    const float tot = (reds[hg][0] + reds[hg][1]) + (reds[hg][2] + reds[hg][3]);
    const int t = tg * 4 + hg;
    out[((size_t)t * B_DIM + b) * S_DIM + s] = e / tot;
}

extern "C" void kernel_launch(void* const* d_in, const int* in_sizes, int n_in,
                              void* d_out, int out_size)
{
    const float* src  = (const float*)d_in[0];
    const int*   mask = (const int*)d_in[1];
    const float* qv   = (const float*)d_in[2];
    const float* Wsrc = (const float*)d_in[3];
    const float* bsrc = (const float*)d_in[4];
    const float* Wq   = (const float*)d_in[5];
    const float* bq   = (const float*)d_in[6];
    const float* w2   = (const float*)d_in[7];
    const float* b2   = (const float*)d_in[8];
    float*       out  = (float*)d_out;

    const int gemm_smem = (2 * 128 * GEMM_PAD + 2 * 64 * GEMM_PAD) * 4;  // 55296
    cudaFuncSetAttribute(proj_gemm, cudaFuncAttributeMaxDynamicSharedMemorySize, gemm_smem);

    dim3 g1(48, 4);
    proj_gemm<<<g1, 512, gemm_smem>>>(src, Wsrc, bsrc, qv, Wq, bq);

    dim3 g2(T_DIM / 4, B_DIM);
    fused_attn<<<g2, 512>>>(w2, b2, mask, out);
}

// round 10
// speedup vs baseline: 1.0439x; 1.0439x over previous
#include <cuda_runtime.h>
#include <cstdint>
#include <math_constants.h>

#define T_DIM 64
#define B_DIM 32
#define S_DIM 128
#define E_DIM 512
#define Q_DIM 512
#define H_DIM 256

#define GEMM_BK   32
#define GEMM_PAD  36   // floats per smem row (32 data + 4 pad): conflict-free frags

// Scratch (device globals — no allocation allowed)
__device__ float g_src_proj[B_DIM * H_DIM * S_DIM];   // [b][h][s]
__device__ float g_q_proj[T_DIM * B_DIM * H_DIM];     // [t][b][h]

__device__ __forceinline__ float ex2f_(float x) {
    float y; asm("ex2.approx.f32 %0, %1;" : "=f"(y) : "f"(x)); return y;
}
__device__ __forceinline__ float tanhf_(float x) {
    float y; asm("tanh.approx.f32 %0, %1;" : "=f"(y) : "f"(x)); return y;
}
__device__ __forceinline__ void mma_tf32(float c[4], const unsigned a[4], const unsigned b[2]) {
    asm volatile(
        "mma.sync.aligned.m16n8k8.row.col.f32.tf32.tf32.f32 "
        "{%0,%1,%2,%3}, {%4,%5,%6,%7}, {%8,%9}, {%0,%1,%2,%3};"
        : "+f"(c[0]), "+f"(c[1]), "+f"(c[2]), "+f"(c[3])
        : "r"(a[0]), "r"(a[1]), "r"(a[2]), "r"(a[3]), "r"(b[0]), "r"(b[1]));
}
__device__ __forceinline__ void cp_async16(uint32_t saddr, const void* gptr) {
    asm volatile("cp.async.cg.shared.global [%0], [%1], 16;" :: "r"(saddr), "l"(gptr));
}

// ---------------------------------------------------------------------------
// Tensor-core projection GEMM — TF32, cp.async double-buffered (unchanged).
// ---------------------------------------------------------------------------
__global__ __launch_bounds__(512) void proj_gemm(
    const float* __restrict__ src, const float* __restrict__ Wsrc, const float* __restrict__ bsrc,
    const float* __restrict__ qv,  const float* __restrict__ Wq,   const float* __restrict__ bq)
{
    extern __shared__ float sm[];
    float* As = sm;                        // [2][128][GEMM_PAD]
    float* Bs = sm + 2 * 128 * GEMM_PAD;   // [2][64][GEMM_PAD]

    const int bx = blockIdx.x;      // 0..47
    const int n0 = blockIdx.y * 64; // h tile base

    const bool is_src = (bx < 32);
    const float* __restrict__ A    = is_src ? (src + (size_t)bx * 128 * E_DIM)
                                            : (qv  + (size_t)(bx - 32) * 128 * Q_DIM);
    const float* __restrict__ W    = is_src ? Wsrc : Wq;
    const float* __restrict__ bias = is_src ? bsrc : bq;

    const int tid  = threadIdx.x;
    const int warp = tid >> 5;
    const int lane = tid & 31;
    const int wm   = (warp & 3) * 32;
    const int wn   = (warp >> 2) * 16;
    const int frow = lane >> 2;
    const int fcol = lane & 3;

    const uint32_t As_base = (uint32_t)__cvta_generic_to_shared(As);
    const uint32_t Bs_base = (uint32_t)__cvta_generic_to_shared(Bs);

    float acc[2][2][4];
#pragma unroll
    for (int i = 0; i < 2; i++)
#pragma unroll
        for (int j = 0; j < 2; j++)
#pragma unroll
            for (int r = 0; r < 4; r++) acc[i][j][r] = 0.f;

    auto load_chunk = [&](int kc, int buf) {
        const int kt = kc * GEMM_BK;
        const uint32_t abuf = As_base + (uint32_t)buf * 128 * GEMM_PAD * 4;
        const uint32_t bbuf = Bs_base + (uint32_t)buf * 64 * GEMM_PAD * 4;
#pragma unroll
        for (int j = 0; j < 2; j++) {
            const int v = tid + j * 512;
            const int r = v >> 3;
            const int c = (v & 7) * 4;
            cp_async16(abuf + (uint32_t)(r * GEMM_PAD + c) * 4,
                       &A[(size_t)r * 512 + kt + c]);
        }
        {
            const int r = tid >> 3;
            const int c = (tid & 7) * 4;
            cp_async16(bbuf + (uint32_t)(r * GEMM_PAD + c) * 4,
                       &W[(size_t)(n0 + r) * 512 + kt + c]);
        }
        asm volatile("cp.async.commit_group;");
    };

    load_chunk(0, 0);

    for (int kc = 0; kc < 16; kc++) {
        if (kc + 1 < 16) {
            load_chunk(kc + 1, (kc + 1) & 1);
            asm volatile("cp.async.wait_group 1;");
        } else {
            asm volatile("cp.async.wait_group 0;");
        }
        __syncthreads();

        const int buf = kc & 1;
        const float* Ab = As + buf * 128 * GEMM_PAD;
        const float* Bb = Bs + buf * 64 * GEMM_PAD;

#pragma unroll
        for (int ks = 0; ks < 4; ks++) {
            const int k0 = ks * 8;
            unsigned ah[2][4];
#pragma unroll
            for (int mf = 0; mf < 2; mf++) {
                const int m = wm + mf * 16;
                ah[mf][0] = __float_as_uint(Ab[(m + frow    ) * GEMM_PAD + k0 + fcol    ]);
                ah[mf][1] = __float_as_uint(Ab[(m + frow + 8) * GEMM_PAD + k0 + fcol    ]);
                ah[mf][2] = __float_as_uint(Ab[(m + frow    ) * GEMM_PAD + k0 + fcol + 4]);
                ah[mf][3] = __float_as_uint(Ab[(m + frow + 8) * GEMM_PAD + k0 + fcol + 4]);
            }
            unsigned bh[2][2];
#pragma unroll
            for (int nf = 0; nf < 2; nf++) {
                const int n = wn + nf * 8;
                bh[nf][0] = __float_as_uint(Bb[(n + frow) * GEMM_PAD + k0 + fcol    ]);
                bh[nf][1] = __float_as_uint(Bb[(n + frow) * GEMM_PAD + k0 + fcol + 4]);
            }
#pragma unroll
            for (int mf = 0; mf < 2; mf++)
#pragma unroll
                for (int nf = 0; nf < 2; nf++)
                    mma_tf32(acc[mf][nf], ah[mf], bh[nf]);
        }
        __syncthreads();
    }

    const int crow = lane >> 2;
    const int ccol = (lane & 3) * 2;

    if (is_src) {
        const int b = bx;
        float* dst = g_src_proj + (size_t)b * H_DIM * S_DIM;
#pragma unroll
        for (int mf = 0; mf < 2; mf++)
#pragma unroll
            for (int nf = 0; nf < 2; nf++) {
                const int s0  = wm + mf * 16 + crow;
                const int h0g = n0 + wn + nf * 8 + ccol;
                dst[(h0g    ) * S_DIM + s0    ] = acc[mf][nf][0] + bias[h0g    ];
                dst[(h0g + 1) * S_DIM + s0    ] = acc[mf][nf][1] + bias[h0g + 1];
                dst[(h0g    ) * S_DIM + s0 + 8] = acc[mf][nf][2] + bias[h0g    ];
                dst[(h0g + 1) * S_DIM + s0 + 8] = acc[mf][nf][3] + bias[h0g + 1];
            }
    } else {
        const int m0 = (bx - 32) * 128;
#pragma unroll
        for (int mf = 0; mf < 2; mf++)
#pragma unroll
            for (int nf = 0; nf < 2; nf++) {
                const int m   = m0 + wm + mf * 16 + crow;
                const int h0g = n0 + wn + nf * 8 + ccol;
                g_q_proj[(size_t)m * H_DIM + h0g    ]       = acc[mf][nf][0] + bias[h0g    ];
                g_q_proj[(size_t)m * H_DIM + h0g + 1]       = acc[mf][nf][1] + bias[h0g + 1];
                g_q_proj[(size_t)(m + 8) * H_DIM + h0g    ] = acc[mf][nf][2] + bias[h0g    ];
                g_q_proj[(size_t)(m + 8) * H_DIM + h0g + 1] = acc[mf][nf][3] + bias[h0g + 1];
            }
    }
}

// ---------------------------------------------------------------------------
// Fused kernel (TT=4, 512 CTAs), hybrid tanh with FACTORED exponent:
//   tt 0,1: MUFU.TANH directly.
//   tt 2,3: tanh(x) = 1 - 2/(1+e^{2x}), with e^{2x} = E * Eq[t][h] where
//           E = ex2(2*log2e*sv) is computed ONCE per h-iter (shared), and
//           Eq[t][h] = ex2(2*log2e*q) is precomputed in smem at fill time.
//           rcp via bit-magic seed + 2 Newton iterations (FMA pipe, err ~1e-5).
// part rows 2,3 store (sum_w_quarter - 2*sum(w*r)).
// ---------------------------------------------------------------------------
__global__ __launch_bounds__(512) void fused_attn(
    const float* __restrict__ w2, const float* __restrict__ b2p,
    const int* __restrict__ mask, float* __restrict__ out)
{
    const int b   = blockIdx.y;
    const int tg  = blockIdx.x;
    const int tid = threadIdx.x;
    const int s   = tid & 127;
    const int hg  = tid >> 7;

    __shared__ float qs[4][H_DIM];        // rows 0,1: q; rows 2,3: Eq = 2^(2q*log2e)
    __shared__ float w2s[H_DIM];
    __shared__ float part[4][4][S_DIM];
    __shared__ float redm[4][4];
    __shared__ float reds[4][4];

    const float LOG2E     = 1.442695040888963407f;
    const float TWO_LOG2E = 2.885390081777926815f;

    for (int idx = tid; idx < 4 * H_DIM; idx += 512) {
        const int tt = idx >> 8;
        const int h  = idx & (H_DIM - 1);
        const int t  = tg * 4 + tt;
        const float q = g_q_proj[((size_t)t * B_DIM + b) * H_DIM + h];
        qs[tt][h] = (tt >= 2) ? ex2f_(q * TWO_LOG2E) : q;   // precompute Eq
    }
    if (tid < H_DIM) w2s[tid] = w2[tid];
    __syncthreads();

    const float* __restrict__ srcb = g_src_proj + (size_t)b * H_DIM * S_DIM + s;
    const int h0 = hg * 64;

    float a0 = 0.f, a1 = 0.f, a2 = 0.f, a3 = 0.f, wsum = 0.f;
#pragma unroll 4
    for (int i = 0; i < 64; i++) {
        const int h = h0 + i;
        const float sv = srcb[h * S_DIM];
        const float w  = w2s[h];
        wsum += w;
        // --- TANH path (tt 0,1) ---
        a0 = fmaf(w, tanhf_(sv + qs[0][h]), a0);
        a1 = fmaf(w, tanhf_(sv + qs[1][h]), a1);
        // --- shared-exponent path (tt 2,3): one ex2 for both ---
        const float E = ex2f_(sv * TWO_LOG2E);      // e^{2*sv}
        {
            const float d = fmaf(E, qs[2][h], 1.f); // 1 + e^{2(sv+q2)}
            float r = __uint_as_float(0x7EF311C3u - __float_as_uint(d));
            r = r * fmaf(-d, r, 2.f);
            r = r * fmaf(-d, r, 2.f);
            a2 = fmaf(w, r, a2);
        }
        {
            const float d = fmaf(E, qs[3][h], 1.f);
            float r = __uint_as_float(0x7EF311C3u - __float_as_uint(d));
            r = r * fmaf(-d, r, 2.f);
            r = r * fmaf(-d, r, 2.f);
            a3 = fmaf(w, r, a3);
        }
    }
    part[0][hg][s] = a0;
    part[1][hg][s] = a1;
    part[2][hg][s] = fmaf(-2.f, a2, wsum);
    part[3][hg][s] = fmaf(-2.f, a3, wsum);
    __syncthreads();

    float logit = ((part[hg][0][s] + part[hg][1][s]) +
                   (part[hg][2][s] + part[hg][3][s])) + b2p[0];
    if (mask[b * S_DIM + s] != 0)
        logit = __int_as_float(0xff800000);

    const int lane = tid & 31;
    const int gw   = (tid >> 5) & 3;

    float m = logit;
#pragma unroll
    for (int off = 16; off >= 1; off >>= 1)
        m = fmaxf(m, __shfl_xor_sync(0xffffffffu, m, off));
    if (lane == 0) redm[hg][gw] = m;
    __syncthreads();

    const float bm = fmaxf(fmaxf(redm[hg][0], redm[hg][1]),
                           fmaxf(redm[hg][2], redm[hg][3]));
    const float e = ex2f_((logit - bm) * LOG2E);
    float sum = e;
#pragma unroll
    for (int off = 16; off >= 1; off >>= 1)
        sum += __shfl_xor_sync(0xffffffffu, sum, off);
    if (lane == 0) reds[hg][gw] = sum;
    __syncthreads();

    const float tot = (reds[hg][0] + reds[hg][1]) + (reds[hg][2] + reds[hg][3]);
    const int t = tg * 4 + hg;
    out[((size_t)t * B_DIM + b) * S_DIM + s] = e / tot;
}

extern "C" void kernel_launch(void* const* d_in, const int* in_sizes, int n_in,
                              void* d_out, int out_size)
{
    const float* src  = (const float*)d_in[0];
    const int*   mask = (const int*)d_in[1];
    const float* qv   = (const float*)d_in[2];
    const float* Wsrc = (const float*)d_in[3];
    const float* bsrc = (const float*)d_in[4];
    const float* Wq   = (const float*)d_in[5];
    const float* bq   = (const float*)d_in[6];
    const float* w2   = (const float*)d_in[7];
    const float* b2   = (const float*)d_in[8];
    float*       out  = (float*)d_out;

    const int gemm_smem = (2 * 128 * GEMM_PAD + 2 * 64 * GEMM_PAD) * 4;  // 55296
    cudaFuncSetAttribute(proj_gemm, cudaFuncAttributeMaxDynamicSharedMemorySize, gemm_smem);

    dim3 g1(48, 4);
    proj_gemm<<<g1, 512, gemm_smem>>>(src, Wsrc, bsrc, qv, Wq, bq);

    dim3 g2(T_DIM / 4, B_DIM);
    fused_attn<<<g2, 512>>>(w2, b2, mask, out);
}